// round 16
// baseline (speedup 1.0000x reference)
#include <cuda_runtime.h>
#include <cstdint>

// Problem constants: B=2, N=1024, T=64, H=64
#define NN 1024

// Scratch (allocation-free rule: __device__ globals)
// p/q layout: plain [b][h][n] -> element (b,h,n) at b*65536 + h*1024 + n
__device__ float g_p[2 * 64 * NN];
__device__ float g_q[2 * 64 * NN];
__device__ float g_U[NN];
__device__ float g_V[NN];
__device__ float g_pv[NN * 16];      // per-(row, col-tile) partial max value
__device__ int   g_pi[NN * 16];      // per-(row, col-tile) partial argmax j
// cross-block tail state (reset by last k2 block each run)
__device__ int   g_rowcnt[16];
__device__ int   g_done;

// ---- cp.async helpers ----
__device__ __forceinline__ void cp_async16(uint32_t s, const void* g) {
    asm volatile("cp.async.cg.shared.global [%0], [%1], 16;\n" :: "r"(s), "l"(g));
}
__device__ __forceinline__ void cp_commit() {
    asm volatile("cp.async.commit_group;\n");
}
template <int N>
__device__ __forceinline__ void cp_wait() {
    asm volatile("cp.async.wait_group %0;\n" :: "n"(N));
}

// ---------------------------------------------------------------------------
// Kernel 1: per-node projections. 256 blocks x 256 threads, 4 nodes/block.
// ---------------------------------------------------------------------------
__global__ void __launch_bounds__(256) k1_proj(
    const float* __restrict__ x, const float* __restrict__ W1,
    const float* __restrict__ b1, const float* __restrict__ W2,
    const float* __restrict__ b2) {
    __shared__ __align__(16) float sx[2][4][68];   // x rows, pitch 68
    __shared__ float sUV[2][32];                   // warp partials [sel][w*4+nn]

    const int tid = threadIdx.x;
    const int n0 = blockIdx.x * 4;

    #pragma unroll
    for (int k = 0; k < 2; ++k) {             // x: 512 floats
        int l = k * 256 + tid;
        int b = l >> 8, node = (l >> 6) & 3, t = l & 63;
        sx[b][node][t] = x[((b << 10) + n0 + node) * 64 + t];
    }
    __syncthreads();

    const int h = tid >> 2;       // 0..63
    const int nn = tid & 3;       // 0..3
    const float4* __restrict__ wrow = (const float4*)(W1 + h * 128);

    float p0 = 0.f, p1 = 0.f, q0 = 0.f, q1 = 0.f;
    #pragma unroll
    for (int tt = 0; tt < 16; ++tt) {
        float4 wa = __ldg(&wrow[tt]);
        float4 wb = __ldg(&wrow[16 + tt]);
        float4 xa = *(const float4*)&sx[0][nn][tt * 4];
        float4 xb = *(const float4*)&sx[1][nn][tt * 4];
        p0 = fmaf(xa.x, wa.x, p0); p0 = fmaf(xa.y, wa.y, p0);
        p0 = fmaf(xa.z, wa.z, p0); p0 = fmaf(xa.w, wa.w, p0);
        p1 = fmaf(xb.x, wa.x, p1); p1 = fmaf(xb.y, wa.y, p1);
        p1 = fmaf(xb.z, wa.z, p1); p1 = fmaf(xb.w, wa.w, p1);
        q0 = fmaf(xa.x, wb.x, q0); q0 = fmaf(xa.y, wb.y, q0);
        q0 = fmaf(xa.z, wb.z, q0); q0 = fmaf(xa.w, wb.w, q0);
        q1 = fmaf(xb.x, wb.x, q1); q1 = fmaf(xb.y, wb.y, q1);
        q1 = fmaf(xb.z, wb.z, q1); q1 = fmaf(xb.w, wb.w, q1);
    }
    float bb = __ldg(&b1[h]);
    q0 += bb; q1 += bb;

    g_p[h * 1024 + n0 + nn]         = p0;
    g_p[65536 + h * 1024 + n0 + nn] = p1;
    g_q[h * 1024 + n0 + nn]         = q0;
    g_q[65536 + h * 1024 + n0 + nn] = q1;

    float w2h = __ldg(&W2[h]);
    float ru = w2h * (p0 + p1), rv = w2h * (q0 + q1);
    #pragma unroll
    for (int m = 16; m >= 4; m >>= 1) {
        ru += __shfl_down_sync(0xffffffffu, ru, m);
        rv += __shfl_down_sync(0xffffffffu, rv, m);
    }
    if ((tid & 31) < 4) {
        int w = tid >> 5;
        sUV[0][w * 4 + nn] = ru;
        sUV[1][w * 4 + nn] = rv;
    }
    __syncthreads();
    if (tid < 8) {
        int sel = tid >> 2, n2 = tid & 3;
        float acc = 0.f;
        #pragma unroll
        for (int w = 0; w < 8; ++w) acc += sUV[sel][w * 4 + n2];
        if (sel == 0) g_U[n0 + n2] = 0.2525f * acc;
        else          g_V[n0 + n2] = 0.2525f * acc + __ldg(&b2[0]);
    }
}

// ---------------------------------------------------------------------------
// Kernel 2: pairwise |z| accumulation + fused gumbel/argmax + finisher tail.
// Tile 64x64, grid (16,16) = 256 blocks; block = 512 THREADS (16 warps)
// -> 2 blocks/SM = 8 warps/SMSP on the critical SMs (double R13/R15).
// Per-thread 2i x 4j x 2b = 8 accs; tx = tid&15 (j), ty = tid>>4 (i, 0..31).
// cp.async double-buffered 16-h chunks.
// ---------------------------------------------------------------------------
__global__ void __launch_bounds__(512, 2) k2_pair(const float* __restrict__ W2,
                                                  const float* __restrict__ gu,
                                                  float* __restrict__ out) {
    __shared__ __align__(16) float ps[2][2][16][64];  // [buf][b][h][i]
    __shared__ __align__(16) float qs[2][2][16][64];  // [buf][b][h][j]
    __shared__ float sw[64];
    __shared__ int s_old;

    const int tid = threadIdx.x;
    const int tx = tid & 15, ty = tid >> 4;          // tx: j/4, ty: i/2 (0..31)
    const int bx = blockIdx.x, by = blockIdx.y;
    const int i0 = by * 64, j0 = bx * 64;

    if (tid < 64) sw[tid] = 0.2475f * W2[tid];

    // async fill of chunk c (h in [16c, 16c+16)) into buffer c&1
    // 512 threads, each: 1 ps float4 + 1 qs float4 (512 each total)
    auto fill = [&](int c) {
        const int buf = c & 1, hb = c * 16;
        int b = tid >> 8, hh = (tid >> 4) & 15, f4 = (tid & 15) << 2;
        cp_async16((uint32_t)__cvta_generic_to_shared(&ps[buf][b][hh][f4]),
                   &g_p[b * 65536 + (hb + hh) * 1024 + i0 + f4]);
        cp_async16((uint32_t)__cvta_generic_to_shared(&qs[buf][b][hh][f4]),
                   &g_q[b * 65536 + (hb + hh) * 1024 + j0 + f4]);
        cp_commit();
    };

    fill(0);
    fill(1);

    float acc[2][4];
    #pragma unroll
    for (int r = 0; r < 2; ++r)
        #pragma unroll
        for (int c = 0; c < 4; ++c) acc[r][c] = 0.f;

    float4 gupre[2];   // gu prefetch registers (filled at last chunk)

    #pragma unroll
    for (int c = 0; c < 4; ++c) {
        if (c < 3) cp_wait<1>(); else cp_wait<0>();
        __syncthreads();
        if (c == 3) {   // hide gu latency under last chunk's compute
            #pragma unroll
            for (int r = 0; r < 2; ++r)
                gupre[r] = __ldg((const float4*)&gu[(i0 + (ty << 1) + r) * 1024
                                                    + j0 + (tx << 2)]);
        }
        const int buf = c & 1, hb = c * 16;

        #pragma unroll
        for (int h = 0; h < 16; ++h) {
            float w = sw[hb + h];
            float2 p0v = *(const float2*)&ps[buf][0][h][ty << 1];
            float2 p1v = *(const float2*)&ps[buf][1][h][ty << 1];
            float4 q0v = *(const float4*)&qs[buf][0][h][tx << 2];
            float4 q1v = *(const float4*)&qs[buf][1][h][tx << 2];
            float p0a[2] = {p0v.x, p0v.y};
            float p1a[2] = {p1v.x, p1v.y};
            float q0a[4] = {q0v.x, q0v.y, q0v.z, q0v.w};
            float q1a[4] = {q1v.x, q1v.y, q1v.z, q1v.w};
            #pragma unroll
            for (int r = 0; r < 2; ++r)
                #pragma unroll
                for (int cc = 0; cc < 4; ++cc) {
                    float z0 = p0a[r] + q0a[cc];
                    float z1 = p1a[r] + q1a[cc];
                    acc[r][cc] = fmaf(w, fabsf(z0), acc[r][cc]);
                    acc[r][cc] = fmaf(w, fabsf(z1), acc[r][cc]);
                }
        }

        __syncthreads();
        if (c < 2) fill(c + 2);
    }

    float u[2], v[4];
    #pragma unroll
    for (int r = 0; r < 2; ++r) u[r] = g_U[i0 + (ty << 1) + r];
    #pragma unroll
    for (int c = 0; c < 4; ++c) v[c] = g_V[j0 + (tx << 2) + c];

    // zero-fill this out tile (ones written by the finisher tail)
    const float4 z4 = make_float4(0.f, 0.f, 0.f, 0.f);
    #pragma unroll
    for (int r = 0; r < 2; ++r)
        *(float4*)&out[(i0 + (ty << 1) + r) * 1024 + j0 + (tx << 2)] = z4;

    // gumbel + per-row argmax across the 16 tx lanes (16-lane shfl groups)
    #pragma unroll
    for (int r = 0; r < 2; ++r) {
        const int row = i0 + (ty << 1) + r;
        float4 uu = gupre[r];
        float gq[4];
        gq[0] = -__logf(-__logf(uu.x + 1e-10f) + 1e-10f);
        gq[1] = -__logf(-__logf(uu.y + 1e-10f) + 1e-10f);
        gq[2] = -__logf(-__logf(uu.z + 1e-10f) + 1e-10f);
        gq[3] = -__logf(-__logf(uu.w + 1e-10f) + 1e-10f);
        float bv = -3.0e38f; int bj = 1 << 30;
        #pragma unroll
        for (int c = 0; c < 4; ++c) {
            float val = acc[r][c] + u[r] + v[c] + gq[c];
            int j = j0 + (tx << 2) + c;
            if (val > bv || (val == bv && j < bj)) { bv = val; bj = j; }
        }
        #pragma unroll
        for (int m = 1; m < 16; m <<= 1) {
            float ov = __shfl_xor_sync(0xffffffffu, bv, m);
            int   oj = __shfl_xor_sync(0xffffffffu, bj, m);
            if (ov > bv || (ov == bv && oj < bj)) { bv = ov; bj = oj; }
        }
        if (tx == 0) {
            g_pv[row * 16 + bx] = bv;
            g_pi[row * 16 + bx] = bj;
        }
    }

    // ------- finisher tail: 16th block of row-band reduces + scatters -------
    __threadfence();
    __syncthreads();
    if (tid == 0) s_old = atomicAdd(&g_rowcnt[by], 1);
    __syncthreads();
    if (s_old == 15) {
        __threadfence();               // see all partials + zero-fills
        if (tid < 64) {
            const int row = by * 64 + tid;
            float bv = -3.0e38f; int bj = 1 << 30;
            #pragma unroll
            for (int k4 = 0; k4 < 4; ++k4) {
                float4 v4 = *(const float4*)&g_pv[row * 16 + k4 * 4];
                int4   j4 = *(const int4*)&g_pi[row * 16 + k4 * 4];
                float vv[4] = {v4.x, v4.y, v4.z, v4.w};
                int   jj[4] = {j4.x, j4.y, j4.z, j4.w};
                #pragma unroll
                for (int k = 0; k < 4; ++k)
                    if (vv[k] > bv || (vv[k] == bv && jj[k] < bj)) { bv = vv[k]; bj = jj[k]; }
            }
            out[row * 1024 + bj] = 1.0f;
        }
    }
    // last block overall resets tail state for the next graph replay
    if (tid == 0) {
        int old2 = atomicAdd(&g_done, 1);
        if (old2 == 255) {
            #pragma unroll
            for (int s = 0; s < 16; ++s) g_rowcnt[s] = 0;
            g_done = 0;
        }
    }
}

// ---------------------------------------------------------------------------
extern "C" void kernel_launch(void* const* d_in, const int* in_sizes, int n_in,
                              void* d_out, int out_size) {
    const float* x  = (const float*)d_in[0];   // [2,1024,64]
    const float* W1 = (const float*)d_in[1];   // [64,128]
    const float* b1 = (const float*)d_in[2];   // [64]
    const float* W2 = (const float*)d_in[3];   // [1,64]
    const float* b2 = (const float*)d_in[4];   // [1]
    const float* gu = (const float*)d_in[5];   // [1024,1024]
    float* out = (float*)d_out;                // [1024,1024] fp32

    k1_proj<<<256, 256>>>(x, W1, b1, W2, b2);
    k2_pair<<<dim3(16, 16), dim3(512)>>>(W2, gu, out);
}

// round 17
// speedup vs baseline: 1.1559x; 1.1559x over previous
#include <cuda_runtime.h>
#include <cstdint>

// Problem constants: B=2, N=1024, T=64, H=64
#define NN 1024

// Scratch (allocation-free rule: __device__ globals)
// p/q layout: plain [b][h][n] -> element (b,h,n) at b*65536 + h*1024 + n
__device__ float g_p[2 * 64 * NN];
__device__ float g_q[2 * 64 * NN];
__device__ float g_U[NN];
__device__ float g_V[NN];
__device__ float g_pv[NN * 16];      // per-(row, col-tile) partial max value
__device__ int   g_pi[NN * 16];      // per-(row, col-tile) partial argmax j

// ---- cp.async helpers ----
__device__ __forceinline__ void cp_async16(uint32_t s, const void* g) {
    asm volatile("cp.async.cg.shared.global [%0], [%1], 16;\n" :: "r"(s), "l"(g));
}
__device__ __forceinline__ void cp_commit() {
    asm volatile("cp.async.commit_group;\n");
}
template <int N>
__device__ __forceinline__ void cp_wait() {
    asm volatile("cp.async.wait_group %0;\n" :: "n"(N));
}

// ---------------------------------------------------------------------------
// Kernel 1: per-node projections. 256 blocks x 256 threads, 4 nodes/block.
// ---------------------------------------------------------------------------
__global__ void __launch_bounds__(256) k1_proj(
    const float* __restrict__ x, const float* __restrict__ W1,
    const float* __restrict__ b1, const float* __restrict__ W2,
    const float* __restrict__ b2) {
    __shared__ __align__(16) float sx[2][4][68];   // x rows, pitch 68
    __shared__ float sUV[2][32];                   // warp partials [sel][w*4+nn]

    const int tid = threadIdx.x;
    const int n0 = blockIdx.x * 4;

    #pragma unroll
    for (int k = 0; k < 2; ++k) {             // x: 512 floats
        int l = k * 256 + tid;
        int b = l >> 8, node = (l >> 6) & 3, t = l & 63;
        sx[b][node][t] = x[((b << 10) + n0 + node) * 64 + t];
    }
    __syncthreads();

    const int h = tid >> 2;       // 0..63
    const int nn = tid & 3;       // 0..3
    const float4* __restrict__ wrow = (const float4*)(W1 + h * 128);

    float p0 = 0.f, p1 = 0.f, q0 = 0.f, q1 = 0.f;
    #pragma unroll
    for (int tt = 0; tt < 16; ++tt) {
        float4 wa = __ldg(&wrow[tt]);
        float4 wb = __ldg(&wrow[16 + tt]);
        float4 xa = *(const float4*)&sx[0][nn][tt * 4];
        float4 xb = *(const float4*)&sx[1][nn][tt * 4];
        p0 = fmaf(xa.x, wa.x, p0); p0 = fmaf(xa.y, wa.y, p0);
        p0 = fmaf(xa.z, wa.z, p0); p0 = fmaf(xa.w, wa.w, p0);
        p1 = fmaf(xb.x, wa.x, p1); p1 = fmaf(xb.y, wa.y, p1);
        p1 = fmaf(xb.z, wa.z, p1); p1 = fmaf(xb.w, wa.w, p1);
        q0 = fmaf(xa.x, wb.x, q0); q0 = fmaf(xa.y, wb.y, q0);
        q0 = fmaf(xa.z, wb.z, q0); q0 = fmaf(xa.w, wb.w, q0);
        q1 = fmaf(xb.x, wb.x, q1); q1 = fmaf(xb.y, wb.y, q1);
        q1 = fmaf(xb.z, wb.z, q1); q1 = fmaf(xb.w, wb.w, q1);
    }
    float bb = __ldg(&b1[h]);
    q0 += bb; q1 += bb;

    g_p[h * 1024 + n0 + nn]         = p0;
    g_p[65536 + h * 1024 + n0 + nn] = p1;
    g_q[h * 1024 + n0 + nn]         = q0;
    g_q[65536 + h * 1024 + n0 + nn] = q1;

    float w2h = __ldg(&W2[h]);
    float ru = w2h * (p0 + p1), rv = w2h * (q0 + q1);
    #pragma unroll
    for (int m = 16; m >= 4; m >>= 1) {
        ru += __shfl_down_sync(0xffffffffu, ru, m);
        rv += __shfl_down_sync(0xffffffffu, rv, m);
    }
    if ((tid & 31) < 4) {
        int w = tid >> 5;
        sUV[0][w * 4 + nn] = ru;
        sUV[1][w * 4 + nn] = rv;
    }
    __syncthreads();
    if (tid < 8) {
        int sel = tid >> 2, n2 = tid & 3;
        float acc = 0.f;
        #pragma unroll
        for (int w = 0; w < 8; ++w) acc += sUV[sel][w * 4 + n2];
        if (sel == 0) g_U[n0 + n2] = 0.2525f * acc;
        else          g_V[n0 + n2] = 0.2525f * acc + __ldg(&b2[0]);
    }
}

// ---------------------------------------------------------------------------
// Kernel 2: pairwise |z| accumulation + fused gumbel/argmax partials.
// NO finisher tail, NO __threadfence, NO atomics (dropped: MEMBAR.GPU after
// 16 in-flight STG.128 per thread cost ~4-5us across the grid).
// Tile 64x64, grid (16,16), block 16x16, 4i x 4j x 2b per thread;
// cp.async double-buffered 16-h chunks; conflict-free batch-split smem.
// ---------------------------------------------------------------------------
__global__ void __launch_bounds__(256) k2_pair(const float* __restrict__ W2,
                                               const float* __restrict__ gu,
                                               float* __restrict__ out) {
    __shared__ __align__(16) float ps[2][2][16][64];  // [buf][b][h][i]
    __shared__ __align__(16) float qs[2][2][16][64];  // [buf][b][h][j]
    __shared__ float sw[64];

    const int tx = threadIdx.x, ty = threadIdx.y;
    const int tid = ty * 16 + tx;
    const int bx = blockIdx.x, by = blockIdx.y;
    const int i0 = by * 64, j0 = bx * 64;

    if (tid < 64) sw[tid] = 0.2475f * W2[tid];

    // async fill of chunk c (h in [16c, 16c+16)) into buffer c&1
    auto fill = [&](int c) {
        const int buf = c & 1, hb = c * 16;
        #pragma unroll
        for (int k = 0; k < 2; ++k) {
            int l = k * 256 + tid;
            int b = l >> 8, hh = (l >> 4) & 15, f4 = (l & 15) << 2;
            cp_async16((uint32_t)__cvta_generic_to_shared(&ps[buf][b][hh][f4]),
                       &g_p[b * 65536 + (hb + hh) * 1024 + i0 + f4]);
            cp_async16((uint32_t)__cvta_generic_to_shared(&qs[buf][b][hh][f4]),
                       &g_q[b * 65536 + (hb + hh) * 1024 + j0 + f4]);
        }
        cp_commit();
    };

    fill(0);
    fill(1);

    float acc[4][4];
    #pragma unroll
    for (int r = 0; r < 4; ++r)
        #pragma unroll
        for (int c = 0; c < 4; ++c) acc[r][c] = 0.f;

    float4 gupre[4];   // gu prefetch registers (filled at last chunk)

    #pragma unroll
    for (int c = 0; c < 4; ++c) {
        if (c < 3) cp_wait<1>(); else cp_wait<0>();
        __syncthreads();
        if (c == 3) {   // hide gu latency under last chunk's compute
            #pragma unroll
            for (int r = 0; r < 4; ++r)
                gupre[r] = __ldg((const float4*)&gu[(i0 + (ty << 2) + r) * 1024
                                                    + j0 + (tx << 2)]);
        }
        const int buf = c & 1, hb = c * 16;

        #pragma unroll
        for (int h = 0; h < 16; ++h) {
            float w = sw[hb + h];
            float4 p0v = *(const float4*)&ps[buf][0][h][ty << 2];
            float4 p1v = *(const float4*)&ps[buf][1][h][ty << 2];
            float4 q0v = *(const float4*)&qs[buf][0][h][tx << 2];
            float4 q1v = *(const float4*)&qs[buf][1][h][tx << 2];
            float p0a[4] = {p0v.x, p0v.y, p0v.z, p0v.w};
            float p1a[4] = {p1v.x, p1v.y, p1v.z, p1v.w};
            float q0a[4] = {q0v.x, q0v.y, q0v.z, q0v.w};
            float q1a[4] = {q1v.x, q1v.y, q1v.z, q1v.w};
            #pragma unroll
            for (int r = 0; r < 4; ++r)
                #pragma unroll
                for (int cc = 0; cc < 4; ++cc) {
                    float z0 = p0a[r] + q0a[cc];
                    float z1 = p1a[r] + q1a[cc];
                    acc[r][cc] = fmaf(w, fabsf(z0), acc[r][cc]);
                    acc[r][cc] = fmaf(w, fabsf(z1), acc[r][cc]);
                }
        }

        __syncthreads();
        if (c < 2) fill(c + 2);
    }

    float u[4], v[4];
    #pragma unroll
    for (int r = 0; r < 4; ++r) u[r] = g_U[i0 + (ty << 2) + r];
    #pragma unroll
    for (int c = 0; c < 4; ++c) v[c] = g_V[j0 + (tx << 2) + c];

    // zero-fill this out tile (ones written by k3_fin)
    const float4 z4 = make_float4(0.f, 0.f, 0.f, 0.f);
    #pragma unroll
    for (int r = 0; r < 4; ++r)
        *(float4*)&out[(i0 + (ty << 2) + r) * 1024 + j0 + (tx << 2)] = z4;

    // gumbel (from prefetched registers) + per-row argmax across 16 tx lanes
    #pragma unroll
    for (int r = 0; r < 4; ++r) {
        const int row = i0 + (ty << 2) + r;
        float4 uu = gupre[r];
        float gq[4];
        gq[0] = -__logf(-__logf(uu.x + 1e-10f) + 1e-10f);
        gq[1] = -__logf(-__logf(uu.y + 1e-10f) + 1e-10f);
        gq[2] = -__logf(-__logf(uu.z + 1e-10f) + 1e-10f);
        gq[3] = -__logf(-__logf(uu.w + 1e-10f) + 1e-10f);
        float bv = -3.0e38f; int bj = 1 << 30;
        #pragma unroll
        for (int c = 0; c < 4; ++c) {
            float val = acc[r][c] + u[r] + v[c] + gq[c];
            int j = j0 + (tx << 2) + c;
            if (val > bv || (val == bv && j < bj)) { bv = val; bj = j; }
        }
        #pragma unroll
        for (int m = 1; m < 16; m <<= 1) {
            float ov = __shfl_xor_sync(0xffffffffu, bv, m);
            int   oj = __shfl_xor_sync(0xffffffffu, bj, m);
            if (ov > bv || (ov == bv && oj < bj)) { bv = ov; bj = oj; }
        }
        if (tx == 0) {
            g_pv[row * 16 + bx] = bv;
            g_pi[row * 16 + bx] = bj;
        }
    }
}

// ---------------------------------------------------------------------------
// Kernel 3: reduce 16 tile-partials per row, scatter the one-hot 1.0s.
// ---------------------------------------------------------------------------
__global__ void __launch_bounds__(256) k3_fin(float* __restrict__ out) {
    const int i = blockIdx.x * 256 + threadIdx.x;   // row, grid 4x256
    float bv = -3.0e38f; int bj = 1 << 30;
    #pragma unroll
    for (int k4 = 0; k4 < 4; ++k4) {
        float4 v4 = *(const float4*)&g_pv[i * 16 + k4 * 4];
        int4   j4 = *(const int4*)&g_pi[i * 16 + k4 * 4];
        float vv[4] = {v4.x, v4.y, v4.z, v4.w};
        int   jj[4] = {j4.x, j4.y, j4.z, j4.w};
        #pragma unroll
        for (int k = 0; k < 4; ++k)
            if (vv[k] > bv || (vv[k] == bv && jj[k] < bj)) { bv = vv[k]; bj = jj[k]; }
    }
    out[i * 1024 + bj] = 1.0f;
}

// ---------------------------------------------------------------------------
extern "C" void kernel_launch(void* const* d_in, const int* in_sizes, int n_in,
                              void* d_out, int out_size) {
    const float* x  = (const float*)d_in[0];   // [2,1024,64]
    const float* W1 = (const float*)d_in[1];   // [64,128]
    const float* b1 = (const float*)d_in[2];   // [64]
    const float* W2 = (const float*)d_in[3];   // [1,64]
    const float* b2 = (const float*)d_in[4];   // [1]
    const float* gu = (const float*)d_in[5];   // [1024,1024]
    float* out = (float*)d_out;                // [1024,1024] fp32

    k1_proj<<<256, 256>>>(x, W1, b1, W2, b2);
    k2_pair<<<dim3(16, 16), dim3(16, 16)>>>(W2, gu, out);
    k3_fin<<<4, 256>>>(out);
}